// round 1
// baseline (speedup 1.0000x reference)
#include <cuda_runtime.h>
#include <math.h>

// WaveNet with the reference's "min(s.shape[0])" batch/time mixup:
// output is [B=64, 1, 64]. Only x[:, 0, 0:84] participates.
//
// Per-layer recurrence (h = current feature map, F=2 channels):
//   layers 0-9  (d=1, pad=0): g[t] = cd(h[t],h[t+1]) * sigmoid(cg(...));
//                             h'[t] = h[t+1] + g[t]        (left-crop by 1)
//   layers 10-19(d=2, pad=1): g[t] = cd(h[t-1],h[t+1]) * sigmoid(...),
//                             h[-1] := 0 (true pad boundary);
//                             h'[t] = h[t] + g[t]
// Valid range of h at layer i is exactly [0, 83-i]; conv valid on [0, 82-i].
// Skips accumulate g[t] for t<64; out = conv_out(relu(sum)).

#define N_RES 20
#define W0 84        // x window / h0 length (indices 0..83)

__global__ void __launch_bounds__(96)
wavenet_small_kernel(const float* __restrict__ x,
                     const float* __restrict__ w_in,
                     const float* __restrict__ b_in,
                     const float* __restrict__ wd,
                     const float* __restrict__ bd,
                     const float* __restrict__ wg,
                     const float* __restrict__ bg,
                     const float* __restrict__ w_out,
                     const float* __restrict__ b_out,
                     float* __restrict__ out)
{
    __shared__ float h[2][2][96];   // ping-pong [buf][channel][t]

    const int b = blockIdx.x;       // batch
    const int t = threadIdx.x;      // time index

    // conv_in: 1x1, C=1 -> F=2
    if (t < W0) {
        float xv = x[(size_t)b * 32768 + t];
        h[0][0][t] = w_in[0] * xv + b_in[0];
        h[0][1][t] = w_in[1] * xv + b_in[1];
    }
    float s0 = 0.0f, s1 = 0.0f;     // skip accumulators (thread owns time t)
    int src = 0;
    __syncthreads();

#pragma unroll
    for (int i = 0; i < N_RES; i++) {
        const int hi  = 83 - i;     // highest valid index of h[src]
        const int dst = src ^ 1;
        const bool d1 = (i < 10);   // dilation 1 vs 2

        if (t < hi) {               // conv valid on [0, hi-1]
            float a0, a1, c0, c1;   // left tap (k=0), right tap (k=1) per channel
            if (d1) {
                a0 = h[src][0][t];
                a1 = h[src][1][t];
            } else {
                a0 = (t >= 1) ? h[src][0][t - 1] : 0.0f;
                a1 = (t >= 1) ? h[src][1][t - 1] : 0.0f;
            }
            c0 = h[src][0][t + 1];
            c1 = h[src][1][t + 1];

            const float* wdi = wd + i * 8;   // [f][c][k] strides 4,2,1
            const float* wgi = wg + i * 8;

            float cd0 = fmaf(wdi[0], a0, fmaf(wdi[1], c0,
                        fmaf(wdi[2], a1, fmaf(wdi[3], c1, bd[i * 2 + 0]))));
            float cd1 = fmaf(wdi[4], a0, fmaf(wdi[5], c0,
                        fmaf(wdi[6], a1, fmaf(wdi[7], c1, bd[i * 2 + 1]))));
            float cg0 = fmaf(wgi[0], a0, fmaf(wgi[1], c0,
                        fmaf(wgi[2], a1, fmaf(wgi[3], c1, bg[i * 2 + 0]))));
            float cg1 = fmaf(wgi[4], a0, fmaf(wgi[5], c0,
                        fmaf(wgi[6], a1, fmaf(wgi[7], c1, bg[i * 2 + 1]))));

            float g0 = cd0 * (1.0f / (1.0f + expf(-cg0)));
            float g1 = cd1 * (1.0f / (1.0f + expf(-cg1)));

            if (t < 64) { s0 += g0; s1 += g1; }

            // residual: d=1 crops left by 1; d=2 keeps alignment
            float r0 = d1 ? c0 : h[src][0][t];
            float r1 = d1 ? c1 : h[src][1][t];
            h[dst][0][t] = r0 + g0;
            h[dst][1][t] = r1 + g1;
        }
        src = dst;
        __syncthreads();
    }

    if (t < 64) {
        float o = fmaf(w_out[0], fmaxf(s0, 0.0f),
                  fmaf(w_out[1], fmaxf(s1, 0.0f), b_out[0]));
        out[(size_t)b * 64 + t] = o;
    }
}

extern "C" void kernel_launch(void* const* d_in, const int* in_sizes, int n_in,
                              void* d_out, int out_size)
{
    const float* x     = (const float*)d_in[0];
    const float* w_in  = (const float*)d_in[1];
    const float* b_in  = (const float*)d_in[2];
    const float* wd    = (const float*)d_in[3];
    const float* bd    = (const float*)d_in[4];
    const float* wg    = (const float*)d_in[5];
    const float* bg    = (const float*)d_in[6];
    const float* w_out = (const float*)d_in[7];
    const float* b_out = (const float*)d_in[8];
    float* out = (float*)d_out;

    wavenet_small_kernel<<<64, 96>>>(x, w_in, b_in, wd, bd, wg, bg,
                                     w_out, b_out, out);
}

// round 2
// speedup vs baseline: 1.4388x; 1.4388x over previous
#include <cuda_runtime.h>
#include <math.h>

// WaveNet with the reference's "min(s.shape[0])" batch/time mixup:
// output is [B=64, 1, 64]. Only x[:, 0, 0:84] participates.
//
// R2 changes vs R1 (12.8us):
//  - all layer weights staged to SMEM once (kills 20 serialized L2-latency
//    weight fetches per replay; L1D is flushed every launch on sm_103a)
//  - __expf + __fdividef sigmoid (2 MUFUs vs ~20-instr accurate expf chain)
//  - __launch_bounds__(96,1): no 32-reg cap, ptxas can pipeline weight LDS

#define N_RES 20
#define W0 84

__global__ void __launch_bounds__(96, 1)
wavenet_small_kernel(const float* __restrict__ x,
                     const float* __restrict__ w_in,
                     const float* __restrict__ b_in,
                     const float* __restrict__ wd,
                     const float* __restrict__ bd,
                     const float* __restrict__ wg,
                     const float* __restrict__ bg,
                     const float* __restrict__ w_out,
                     const float* __restrict__ b_out,
                     float* __restrict__ out)
{
    __shared__ float h[2][2][96];        // ping-pong [buf][channel][t]
    __shared__ float swd[N_RES * 8];     // dilated conv weights
    __shared__ float swg[N_RES * 8];     // gate conv weights
    __shared__ float sbd[N_RES * 2];
    __shared__ float sbg[N_RES * 2];

    const int b = blockIdx.x;            // batch
    const int t = threadIdx.x;           // time index

    // ---- stage weights: 400 floats, parallel, one DRAM/L2 round trip ----
    for (int k = t; k < N_RES * 8; k += 96) { swd[k] = wd[k]; swg[k] = wg[k]; }
    if (t < N_RES * 2) { sbd[t] = bd[t]; sbg[t] = bg[t]; }

    // conv_in: 1x1, C=1 -> F=2
    if (t < W0) {
        float xv = x[(size_t)b * 32768 + t];
        h[0][0][t] = fmaf(w_in[0], xv, b_in[0]);
        h[0][1][t] = fmaf(w_in[1], xv, b_in[1]);
    }
    float s0 = 0.0f, s1 = 0.0f;          // skip accumulators
    int src = 0;
    __syncthreads();

#pragma unroll
    for (int i = 0; i < N_RES; i++) {
        const int hi  = 83 - i;          // highest valid index of h[src]
        const int dst = src ^ 1;
        const bool d1 = (i < 10);        // dilation 1 vs 2

        if (t < hi) {                    // conv valid on [0, hi-1]
            float a0, a1, c0, c1;        // left tap, right tap per channel
            if (d1) {
                a0 = h[src][0][t];
                a1 = h[src][1][t];
            } else {
                a0 = (t >= 1) ? h[src][0][t - 1] : 0.0f;
                a1 = (t >= 1) ? h[src][1][t - 1] : 0.0f;
            }
            c0 = h[src][0][t + 1];
            c1 = h[src][1][t + 1];

            const float* wdi = swd + i * 8;   // [f][c][k] strides 4,2,1
            const float* wgi = swg + i * 8;

            float cd0 = fmaf(wdi[0], a0, fmaf(wdi[1], c0,
                        fmaf(wdi[2], a1, fmaf(wdi[3], c1, sbd[i * 2 + 0]))));
            float cd1 = fmaf(wdi[4], a0, fmaf(wdi[5], c0,
                        fmaf(wdi[6], a1, fmaf(wdi[7], c1, sbd[i * 2 + 1]))));
            float cg0 = fmaf(wgi[0], a0, fmaf(wgi[1], c0,
                        fmaf(wgi[2], a1, fmaf(wgi[3], c1, sbg[i * 2 + 0]))));
            float cg1 = fmaf(wgi[4], a0, fmaf(wgi[5], c0,
                        fmaf(wgi[6], a1, fmaf(wgi[7], c1, sbg[i * 2 + 1]))));

            // fast sigmoid: g = cd / (1 + e^-cg); 2 MUFUs on the chain
            float g0 = __fdividef(cd0, 1.0f + __expf(-cg0));
            float g1 = __fdividef(cd1, 1.0f + __expf(-cg1));

            if (t < 64) { s0 += g0; s1 += g1; }

            // residual: d=1 crops left by 1; d=2 keeps alignment
            float r0 = d1 ? c0 : h[src][0][t];
            float r1 = d1 ? c1 : h[src][1][t];
            h[dst][0][t] = r0 + g0;
            h[dst][1][t] = r1 + g1;
        }
        src = dst;
        __syncthreads();
    }

    if (t < 64) {
        float o = fmaf(w_out[0], fmaxf(s0, 0.0f),
                  fmaf(w_out[1], fmaxf(s1, 0.0f), b_out[0]));
        out[(size_t)b * 64 + t] = o;
    }
}

extern "C" void kernel_launch(void* const* d_in, const int* in_sizes, int n_in,
                              void* d_out, int out_size)
{
    const float* x     = (const float*)d_in[0];
    const float* w_in  = (const float*)d_in[1];
    const float* b_in  = (const float*)d_in[2];
    const float* wd    = (const float*)d_in[3];
    const float* bd    = (const float*)d_in[4];
    const float* wg    = (const float*)d_in[5];
    const float* bg    = (const float*)d_in[6];
    const float* w_out = (const float*)d_in[7];
    const float* b_out = (const float*)d_in[8];
    float* out = (float*)d_out;

    wavenet_small_kernel<<<64, 96>>>(x, w_in, b_in, wd, bd, wg, bg,
                                     w_out, b_out, out);
}